// round 6
// baseline (speedup 1.0000x reference)
#include <cuda_runtime.h>
#include <cstdint>

#define BB 4
#define FF 3
#define NPTS 8192
#define DD 16
#define KNN_K 32
#define OO 64
#define ALPHA 0.2f

#define NB 256                      // x-axis buckets
#define XMINV (-5.0f)
#define BWID 0.0390625f             // 10/256 = 5*2^-7, exact binary
#define INV_BWID 25.6f
#define PRUNE_MARGIN 1e-3f

#define QPW 4                       // queries per warp (sorted-adjacent)
#define KNN_WARPS 8                 // warps per knn block
#define PRE_BLOCKS 128              // 128 * 256 = 32768 = B*N

// Scratch (device globals -- no allocations allowed)
__device__ float  g_y1[BB * NPTS * OO];         // W1 . x[:,m]       [b][m][o]
__device__ float  g_c [BB * NPTS * OO];         // (W2-W1).x[:,n]    [b][n][o]
__device__ int    g_idx[BB * NPTS * KNN_K];     // knn indices
__device__ float4 g_spts[BB * NPTS];            // x-sorted (p0,p1,p2, idx-bits)
__device__ int    g_bstart[BB * (NB + 1)];      // bucket CSR offsets

// ---------------------------------------------------------------------------
__device__ __forceinline__ int bucket_of(float xv)
{
    int bk = (int)floorf((xv - XMINV) * INV_BWID);
    return min(max(bk, 0), NB - 1);
}

// order-preserving float->u32 map and inverse
__device__ __forceinline__ unsigned mapf(float dpos)
{
    unsigned ub = __float_as_uint(dpos);
    return ub ^ (((unsigned)((int)ub >> 31)) | 0x80000000u);
}
__device__ __forceinline__ float unmapf(unsigned m)
{
    unsigned ub = (m & 0x80000000u) ? (m ^ 0x80000000u) : ~m;
    return __uint_as_float(ub);
}

// Warp-cooperative sorted insert into lane-distributed top-32 (warp-converged).
__device__ __forceinline__ void insert32(unsigned long long key,
                                         unsigned long long& listk,
                                         unsigned long long& worst,
                                         int lane)
{
    const unsigned FULL = 0xFFFFFFFFu;
    unsigned pass = __ballot_sync(FULL, key < worst);
    while (pass) {
        int src = __ffs(pass) - 1;
        pass &= pass - 1;
        unsigned long long bk = __shfl_sync(FULL, key, src);
        if (bk < worst) {                       // uniform branch
            unsigned long long up = __shfl_up_sync(FULL, listk, 1);
            bool gt   = listk > bk;
            bool upgt = (lane > 0) && (up > bk);
            if (gt) listk = upgt ? up : bk;
            worst = __shfl_sync(FULL, listk, 31);
        }
    }
}

// ---------------------------------------------------------------------------
// Kernel A: per-batch counting sort of points by x into NB buckets.
// Parallel Hillis-Steele scan (no serial tid==0 loop).
// ---------------------------------------------------------------------------
__global__ __launch_bounds__(1024) void sort_kernel(const float* __restrict__ points)
{
    __shared__ int hist[NB];
    __shared__ int scn[NB];
    int b = blockIdx.x;
    int tid = threadIdx.x;
    const float* pb = points + b * FF * NPTS;

    if (tid < NB) hist[tid] = 0;
    __syncthreads();

    for (int m = tid; m < NPTS; m += 1024)
        atomicAdd(&hist[bucket_of(pb[m])], 1);
    __syncthreads();

    if (tid < NB) scn[tid] = hist[tid];
    __syncthreads();
#pragma unroll
    for (int off = 1; off < NB; off <<= 1) {
        int v = (tid < NB && tid >= off) ? scn[tid - off] : 0;
        __syncthreads();
        if (tid < NB) scn[tid] += v;
        __syncthreads();
    }
    if (tid < NB) {
        int ex = scn[tid] - hist[tid];          // exclusive
        g_bstart[b * (NB + 1) + tid] = ex;
        hist[tid] = ex;                          // scatter cursor
    }
    if (tid == 0) g_bstart[b * (NB + 1) + NB] = NPTS;
    __syncthreads();

    for (int m = tid; m < NPTS; m += 1024) {
        float a0 = pb[m];
        int bk = bucket_of(a0);
        int pos = atomicAdd(&hist[bk], 1);
        g_spts[b * NPTS + pos] =
            make_float4(a0, pb[NPTS + m], pb[2 * NPTS + m], __int_as_float(m));
    }
}

// ---------------------------------------------------------------------------
// Kernel B (fused): blocks [0,PRE_BLOCKS) = feature projections;
// rest = pruned 32-NN, 4 sorted-adjacent queries per warp.
//
// Distance arithmetic bit-identical to verified rounds:
//   xx   = fl(fl(fl(p0^2)+fl(p1^2))+fl(p2^2))
//   dpos = fsub(xx_m, fma(s, 2, -xx_n))
//   key  = <mapf(dpos), idx>   (unique; stable ties like lax.top_k)
// Per-query axis prune identical to R5 (conservative; clamped-edge safe;
// sentinel worst -> NaN -> no early stop before 32 real neighbors).
// Selection is order-invariant, so the slab UNION across 4 queries is a
// harmless superset => results identical to brute force.
// ---------------------------------------------------------------------------
__global__ __launch_bounds__(256) void fused_pre_knn_kernel(
    const float* __restrict__ points,
    const float* __restrict__ x,
    const float* __restrict__ W)
{
    __shared__ float sW[OO * 2 * DD];           // precompute blocks
    __shared__ int   sbs[NB + 1];               // knn blocks: bucket CSR

    int tid = threadIdx.x;

    if (blockIdx.x < PRE_BLOCKS) {
        for (int i = tid; i < OO * 2 * DD; i += 256) sW[i] = W[i];
        __syncthreads();

        int gid = blockIdx.x * 256 + tid;       // over B*N
        int b = gid / NPTS, n = gid % NPTS;

        float xv[DD];
#pragma unroll
        for (int d = 0; d < DD; d++) xv[d] = x[(b * DD + d) * NPTS + n];

        float* y1p = &g_y1[(b * NPTS + n) * OO];
        float* cp  = &g_c [(b * NPTS + n) * OO];
#pragma unroll 4
        for (int o = 0; o < OO; o++) {
            float s1 = 0.f, s2 = 0.f;
#pragma unroll
            for (int d = 0; d < DD; d++) {
                s1 = __fmaf_rn(sW[o * 2 * DD + d],      xv[d], s1);
                s2 = __fmaf_rn(sW[o * 2 * DD + DD + d], xv[d], s2);
            }
            y1p[o] = s1;
            cp[o]  = s2 - s1;
        }
        return;
    }

    // ---------------- knn: 4 sorted-adjacent queries per warp -------------
    int bid  = blockIdx.x - PRE_BLOCKS;          // 0 .. BB*256-1
    int b    = bid >> 8;                         // / 256 blocks per batch
    int wblk = bid & 255;
    int wid  = tid >> 5;
    int lane = tid & 31;
    int gw   = wblk * KNN_WARPS + wid;           // per-batch warp id 0..2047
    int pos0 = gw * QPW;                         // sorted positions [pos0,pos0+4)

    for (int j = tid; j < NB + 1; j += 256)
        sbs[j] = g_bstart[b * (NB + 1) + j];
    __syncthreads();

    const float4* sp = g_spts + b * NPTS;

    // fetch the 4 queries (lanes 0-3), broadcast
    float4 qd = make_float4(0.f, 0.f, 0.f, 0.f);
    if (lane < QPW) qd = sp[pos0 + lane];

    float q0[QPW], q1[QPW], q2[QPW], nxxn[QPW];
    int   qorig[QPW], qb[QPW];
    const unsigned FULL = 0xFFFFFFFFu;
#pragma unroll
    for (int qi = 0; qi < QPW; qi++) {
        q0[qi] = __shfl_sync(FULL, qd.x, qi);
        q1[qi] = __shfl_sync(FULL, qd.y, qi);
        q2[qi] = __shfl_sync(FULL, qd.z, qi);
        qorig[qi] = __shfl_sync(FULL, __float_as_int(qd.w), qi);
        float xxn = __fadd_rn(
            __fadd_rn(__fmul_rn(q0[qi], q0[qi]), __fmul_rn(q1[qi], q1[qi])),
            __fmul_rn(q2[qi], q2[qi]));
        nxxn[qi] = -xxn;
        qb[qi] = bucket_of(q0[qi]);
    }

    unsigned long long listk[QPW], worst[QPW];
#pragma unroll
    for (int qi = 0; qi < QPW; qi++) {
        listk[qi] = 0xFFFFFFFF00000000ULL | (unsigned)lane;
        worst[qi] = 0xFFFFFFFF0000001FULL;
    }

    // process one bucket for the subset of queries in wantmask
    auto process = [&](int j, unsigned wantmask) {
        int s0 = sbs[j], s1e = sbs[j + 1];
        for (int g = s0; g < s1e; g += 32) {
            int i = g + lane;
            float4 c = make_float4(0.f, 0.f, 0.f, 0.f);
            bool valid = (i < s1e);
            if (valid) c = __ldg(&sp[i]);
            float xxm = __fadd_rn(
                __fadd_rn(__fmul_rn(c.x, c.x), __fmul_rn(c.y, c.y)),
                __fmul_rn(c.z, c.z));
            unsigned cidx = (unsigned)__float_as_int(c.w);
#pragma unroll
            for (int qi = 0; qi < QPW; qi++) {
                if (wantmask & (1u << qi)) {     // warp-uniform
                    float ss = __fmul_rn(q0[qi], c.x);
                    ss = __fmaf_rn(q1[qi], c.y, ss);
                    ss = __fmaf_rn(q2[qi], c.z, ss);
                    float d = __fsub_rn(xxm, __fmaf_rn(ss, 2.0f, nxxn[qi]));
                    unsigned long long key = valid
                        ? (((unsigned long long)mapf(d) << 32) | cidx)
                        : 0xFFFFFFFFFFFFFFFFULL;
                    insert32(key, listk[qi], worst[qi], lane);
                }
            }
        }
    };

    // initial range covers all 4 own buckets
    int lb = qb[0], rb = qb[0];
#pragma unroll
    for (int qi = 1; qi < QPW; qi++) {
        lb = min(lb, qb[qi]);
        rb = max(rb, qb[qi]);
    }
    for (int j = lb; j <= rb; j++) process(j, 0xFu);

    int l = lb - 1, r = rb + 1;
    unsigned maskL = (l >= 0) ? 0xFu : 0u;
    unsigned maskR = (r < NB) ? 0xFu : 0u;
    while (maskL | maskR) {
        if (maskR) {
            float edge = XMINV + (float)r * BWID;      // exact
#pragma unroll
            for (int qi = 0; qi < QPW; qi++) {
                if (maskR & (1u << qi)) {
                    float worstd = unmapf((unsigned)(worst[qi] >> 32));
                    float dx = __fsub_rn(edge, q0[qi]);
                    if (__fmul_rn(dx, dx) > worstd + PRUNE_MARGIN)
                        maskR &= ~(1u << qi);
                }
            }
            if (maskR) { process(r, maskR); r++; if (r >= NB) maskR = 0; }
        }
        if (maskL) {
            float edge = XMINV + (float)(l + 1) * BWID;  // right edge of l
#pragma unroll
            for (int qi = 0; qi < QPW; qi++) {
                if (maskL & (1u << qi)) {
                    float worstd = unmapf((unsigned)(worst[qi] >> 32));
                    float dx = __fsub_rn(q0[qi], edge);
                    if (__fmul_rn(dx, dx) > worstd + PRUNE_MARGIN)
                        maskL &= ~(1u << qi);
                }
            }
            if (maskL) { process(l, maskL); l--; if (l < 0) maskL = 0; }
        }
    }

#pragma unroll
    for (int qi = 0; qi < QPW; qi++)
        g_idx[(b * NPTS + qorig[qi]) * KNN_K + lane] =
            (int)(listk[qi] & 0xFFFFFFFFu);
}

// ---------------------------------------------------------------------------
// Kernel 3: out[b][o][n] = (1/K) * sum_k leaky( y1[b][idx[n][k]][o] + c[b][n][o] )
// ---------------------------------------------------------------------------
__global__ __launch_bounds__(256) void edgeconv_kernel(float* __restrict__ out)
{
    __shared__ float stile[OO][33];
    __shared__ int   sidx[32 * KNN_K];

    int b = blockIdx.y;
    int nbase = blockIdx.x * 32;
    int tid = threadIdx.x;

    for (int i = tid; i < 32 * KNN_K; i += 256)
        sidx[i] = g_idx[(b * NPTS + nbase) * KNN_K + i];
    __syncthreads();

    int o = tid & 63;
    int sub = tid >> 6;

    for (int nt = 0; nt < 8; nt++) {
        int nl = nt * 4 + sub;
        int n = nbase + nl;
        float c = g_c[(b * NPTS + n) * OO + o];
        float acc = 0.f;
        const int* ip = &sidx[nl * KNN_K];
#pragma unroll 8
        for (int k = 0; k < KNN_K; k++) {
            int m = ip[k];
            float t = g_y1[(b * NPTS + m) * OO + o] + c;
            acc += (t >= 0.f) ? t : ALPHA * t;
        }
        stile[o][nl] = acc * (1.0f / KNN_K);
    }
    __syncthreads();

#pragma unroll
    for (int r = 0; r < 8; r++) {
        int oo = r * 8 + (tid >> 5);
        int nn = tid & 31;
        out[(b * OO + oo) * NPTS + nbase + nn] = stile[oo][nn];
    }
}

// ---------------------------------------------------------------------------
extern "C" void kernel_launch(void* const* d_in, const int* in_sizes, int n_in,
                              void* d_out, int out_size)
{
    const float* points = nullptr;
    const float* x = nullptr;
    const float* W = nullptr;
    for (int i = 0; i < n_in; i++) {
        if      (in_sizes[i] == BB * FF * NPTS) points = (const float*)d_in[i];
        else if (in_sizes[i] == BB * DD * NPTS) x      = (const float*)d_in[i];
        else if (in_sizes[i] == OO * 2 * DD)    W      = (const float*)d_in[i];
    }
    float* out = (float*)d_out;

    sort_kernel<<<BB, 1024>>>(points);

    int knn_blocks = BB * (NPTS / (QPW * KNN_WARPS));  // 4 * 256 = 1024
    fused_pre_knn_kernel<<<PRE_BLOCKS + knn_blocks, 256>>>(points, x, W);

    edgeconv_kernel<<<dim3(NPTS / 32, BB), 256>>>(out);
}